// round 10
// baseline (speedup 1.0000x reference)
#include <cuda_runtime.h>

#define NUM_R 725
#define NUM_T 180
#define IMG_N 512
#define NSPLIT 4                 // n-dimension split (720 blocks = 1 wave @5/SM)
#define TB 256                   // threads per block
#define NROWS (IMG_N / NSPLIT)   // 128 sweep rows per block
#define CHUNK 8                  // rows per pipeline stage
#define ROWSTRIDE 516            // 512 data + 4 pad floats (16B-aligned)
#define NCHUNK (NROWS / CHUNK)   // 16 stages

// Scratch (device globals per the allocation-free rule)
__device__ float g_imgT[IMG_N * IMG_N];                 // transposed image
__device__ float g_scratch[NSPLIT * NUM_T * NUM_R];     // partials [sp][t][r]

// ---- cp.async helpers ------------------------------------------------------
__device__ __forceinline__ void cpasync16(void* smem, const void* gmem) {
    unsigned sa = (unsigned)__cvta_generic_to_shared(smem);
    asm volatile("cp.async.cg.shared.global [%0], [%1], 16;" :: "r"(sa), "l"(gmem));
}
__device__ __forceinline__ void cpasync_commit() {
    asm volatile("cp.async.commit_group;");
}
template <int N>
__device__ __forceinline__ void cpasync_wait() {
    asm volatile("cp.async.wait_group %0;" :: "n"(N));
}

// ---------------------------------------------------------------------------
// Transpose: g_imgT[a*512 + b] = img[b*512 + a]   (so y-sweep reads rows)
// ---------------------------------------------------------------------------
__global__ void dht_transpose(const float* __restrict__ img) {
    __shared__ float tile[32][33];
    int bx = blockIdx.x * 32, by = blockIdx.y * 32;
    int tx = threadIdx.x, ty = threadIdx.y;
#pragma unroll
    for (int i = 0; i < 32; i += 8)
        tile[ty + i][tx] = img[(by + ty + i) * IMG_N + (bx + tx)];
    __syncthreads();
#pragma unroll
    for (int i = 0; i < 32; i += 8)
        g_imgT[(bx + ty + i) * IMG_N + (by + tx)] = tile[tx][ty + i];
}

// ---------------------------------------------------------------------------
// Main Hough kernel. blockIdx.x = theta, blockIdx.y = n-split.
// Thread tid owns rhos {tid, tid+256, tid+512}: warp w covers 3 spread
// 32-bin groups (base 32w + 256k). Per chunk, each group gets its own
// warp-uniform 4-corner band test; dead groups (all samples OOB -> +0.0f)
// are skipped. The spread mapping balances live work across ALL warps, so
// the barrier-phased critical path shrinks with the skip rate.
// Zero-padded smem rows (row[512]=0): OOB index -> min(u,512) -> reads 0.
// ---------------------------------------------------------------------------
__global__ __launch_bounds__(TB, 5) void dht_main(const float* __restrict__ img) {
    __shared__ float buf[2][CHUNK * ROWSTRIDE];   // 33 KB total

    const int t   = blockIdx.x;
    const int sp  = blockIdx.y;
    const int tid = threadIdx.x;
    const int w   = tid >> 5;

    // theta = t * f32(pi/180); libdevice cos/sin on the identical f32 theta.
    const float theta = __fmul_rn((float)t, 0.017453292519943295f);
    const float c = cosf(theta);
    const float s = sinf(theta);
    const bool use_x = fabsf(s) >= fabsf(c);

    const float* __restrict__ src = use_x ? img : g_imgT;
    const float den  = use_x ? s : c;
    const float coef = use_x ? c : s;

    const float rden  = __fdiv_rn(1.0f, den);   // correctly-rounded seed
    const float nden  = -den;
    const float ncoef = -coef;

    // rho table: f32 linspace(-diag, diag, 725).
    const float diag  = __fsqrt_rn(524288.0f);
    const float delta = __fdiv_rn(__fadd_rn(diag, diag), 724.0f);
    const float ndiag = -diag;

    const int r0 = tid, r1 = tid + TB, r2 = tid + 2 * TB;
    const float rho0 = (r0 == NUM_R - 1) ? diag : __fadd_rn(ndiag, __fmul_rn((float)r0, delta));
    const float rho1 = (r1 == NUM_R - 1) ? diag : __fadd_rn(ndiag, __fmul_rn((float)r1, delta));
    const float rho2 = (r2 == NUM_R - 1) ? diag : __fadd_rn(ndiag, __fmul_rn((float)r2, delta));

    // Warp-uniform rho bounds per group (+/- 1 bin slack each side).
    const float gA0 = ndiag + ((float)(32 * w)       - 1.0f) * delta;
    const float gB0 = ndiag + ((float)(32 * w)       + 32.0f) * delta;
    const float gA1 = ndiag + ((float)(32 * w + 256) - 1.0f) * delta;
    const float gB1 = ndiag + ((float)(32 * w + 256) + 32.0f) * delta;
    const float gA2 = ndiag + ((float)(32 * w + 512) - 1.0f) * delta;
    const float gB2 = ndiag + ((float)(32 * w + 512) + 32.0f) * delta;
    const bool g2exists = (32 * w + 512) <= (NUM_R - 1);   // warp 7: all r2 >= 725

    const int nbase0 = sp * NROWS;

    float acc0 = 0.0f, acc1 = 0.0f, acc2 = 0.0f;

    // Zero the pad slots of both buffers once (cp.async never touches them).
    if (tid < 2 * CHUNK) {
        int b = tid >> 3, j = tid & 7;
        *(float4*)(&buf[b][j * ROWSTRIDE + IMG_N]) = make_float4(0.f, 0.f, 0.f, 0.f);
    }

    const float4* __restrict__ gbase = (const float4*)(src + (size_t)nbase0 * IMG_N);

    // Prologue: prefetch chunk 0 into buffer 0.
    {
#pragma unroll
        for (int l = 0; l < 4; l++) {
            int idx = tid + l * TB;            // 0..1023
            int jr = idx >> 7, cx = idx & 127;
            cpasync16(&((float4*)(&buf[0][jr * ROWSTRIDE]))[cx], &gbase[idx]);
        }
        cpasync_commit();
    }

    for (int cb = 0; cb < NCHUNK; cb++) {
        if (cb + 1 < NCHUNK) {                 // prefetch next chunk
            const float4* g = gbase + (size_t)(cb + 1) * CHUNK * (IMG_N / 4);
            float* bnext = buf[(cb + 1) & 1];
#pragma unroll
            for (int l = 0; l < 4; l++) {
                int idx = tid + l * TB;
                int jr = idx >> 7, cx = idx & 127;
                cpasync16(&((float4*)(bnext + jr * ROWSTRIDE))[cx], &g[idx]);
            }
            cpasync_commit();
            cpasync_wait<1>();                 // chunk cb complete
        } else {
            cpasync_wait<0>();
        }
        __syncthreads();                       // data visible to all warps

        const float n0f = (float)(nbase0 + cb * CHUNK);
        const float n1f = n0f + (float)(CHUNK - 1);
        const float* __restrict__ bcur = buf[cb & 1];

        // Shared per-j products: nnc[j] = RN((n0+j) * (-coef)) = -RN(n*coef).
        float nnc[CHUNK];
        {
            float nf = n0f;
#pragma unroll
            for (int j = 0; j < CHUNK; j++) {
                nnc[j] = __fmul_rn(nf, ncoef);
                nf = __fadd_rn(nf, 1.0f);      // exact (integers < 2^23)
            }
        }

        // Warp-uniform band tests (approx math fine: +/-4 margin vs ulp err).
        const float p0 = n0f * ncoef, p1 = n1f * ncoef;
        const float hi = (float)IMG_N + 4.0f;
#define BANDOK(RA, RB)                                                    \
        ({ float y00 = (RA + p0) * rden, y01 = (RA + p1) * rden;          \
           float y10 = (RB + p0) * rden, y11 = (RB + p1) * rden;          \
           float mn = fminf(fminf(y00, y01), fminf(y10, y11));            \
           float mx = fmaxf(fmaxf(y00, y01), fmaxf(y10, y11));            \
           (mx >= -4.0f) && (mn <= hi); })

        if (BANDOK(gA0, gB0)) {
#pragma unroll
            for (int j = 0; j < CHUNK; j++) {
                float num = __fadd_rn(rho0, nnc[j]);
                float q0  = __fmul_rn(num, rden);
                float q   = __fmaf_rn(__fmaf_rn(nden, q0, num), rden, q0);
                int yi = __float2int_rn(q);
                unsigned u = min((unsigned)yi, (unsigned)IMG_N);
                acc0 = __fadd_rn(acc0, bcur[j * ROWSTRIDE + u]);
            }
        }
        if (BANDOK(gA1, gB1)) {
#pragma unroll
            for (int j = 0; j < CHUNK; j++) {
                float num = __fadd_rn(rho1, nnc[j]);
                float q0  = __fmul_rn(num, rden);
                float q   = __fmaf_rn(__fmaf_rn(nden, q0, num), rden, q0);
                int yi = __float2int_rn(q);
                unsigned u = min((unsigned)yi, (unsigned)IMG_N);
                acc1 = __fadd_rn(acc1, bcur[j * ROWSTRIDE + u]);
            }
        }
        if (g2exists && BANDOK(gA2, gB2)) {
#pragma unroll
            for (int j = 0; j < CHUNK; j++) {
                float num = __fadd_rn(rho2, nnc[j]);
                float q0  = __fmul_rn(num, rden);
                float q   = __fmaf_rn(__fmaf_rn(nden, q0, num), rden, q0);
                int yi = __float2int_rn(q);
                unsigned u = min((unsigned)yi, (unsigned)IMG_N);
                acc2 = __fadd_rn(acc2, bcur[j * ROWSTRIDE + u]);
            }
        }
#undef BANDOK
        __syncthreads();                       // compute done before buffer reuse
    }

    // Partial-sum stores: scratch[sp][t][r]; r0,r1 < 725 always; guard r2.
    float* dst = g_scratch + ((size_t)sp * NUM_T + t) * NUM_R;
    dst[r0] = acc0;
    dst[r1] = acc1;
    if (r2 < NUM_R) dst[r2] = acc2;
}

// ---------------------------------------------------------------------------
// Deterministic reduce over NSPLIT partials; out[r*180 + t].
// ---------------------------------------------------------------------------
__global__ void dht_reduce(float* __restrict__ out) {
    int i = blockIdx.x * 256 + threadIdx.x;     // i = t*NUM_R + r
    if (i < NUM_T * NUM_R) {
        float v = g_scratch[i];
#pragma unroll
        for (int sp = 1; sp < NSPLIT; sp++)
            v = __fadd_rn(v, g_scratch[(size_t)sp * NUM_T * NUM_R + i]);
        int t = i / NUM_R;
        int r = i - t * NUM_R;
        out[r * NUM_T + t] = v;
    }
}

// ---------------------------------------------------------------------------
extern "C" void kernel_launch(void* const* d_in, const int* in_sizes, int n_in,
                              void* d_out, int out_size) {
    const float* img = (const float*)d_in[0];
    float* out = (float*)d_out;

    dht_transpose<<<dim3(IMG_N / 32, IMG_N / 32), dim3(32, 8)>>>(img);
    dht_main<<<dim3(NUM_T, NSPLIT), TB>>>(img);
    dht_reduce<<<(NUM_T * NUM_R + 255) / 256, 256>>>(out);
}

// round 11
// speedup vs baseline: 1.0128x; 1.0128x over previous
#include <cuda_runtime.h>

#define NUM_R 725
#define NUM_T 180
#define IMG_N 512
#define NSPLIT 4                 // n-dimension split (720 blocks = 1 wave @5/SM)
#define TB 256                   // threads per block
#define NROWS (IMG_N / NSPLIT)   // 128 sweep rows per block
#define CHUNK 8                  // rows per pipeline stage
#define ROWSTRIDE 516            // 512 data + 4 pad floats (16B-aligned)
#define NCHUNK (NROWS / CHUNK)   // 16 stages

// Scratch (device globals per the allocation-free rule)
__device__ float g_imgT[IMG_N * IMG_N];                 // transposed image
__device__ float g_scratch[NSPLIT * NUM_T * NUM_R];     // partials [sp][t][r]
__device__ int   g_ticket[NUM_T];                       // arrival counters per theta

typedef unsigned long long ull;

// ---- packed f32x2 helpers (Blackwell) --------------------------------------
__device__ __forceinline__ ull pk2(float lo, float hi) {
    ull r; asm("mov.b64 %0, {%1, %2};" : "=l"(r) : "f"(lo), "f"(hi)); return r;
}
__device__ __forceinline__ void upk2(float& lo, float& hi, ull v) {
    asm("mov.b64 {%0, %1}, %2;" : "=f"(lo), "=f"(hi) : "l"(v));
}
__device__ __forceinline__ ull mul2(ull a, ull b) {
    ull d; asm("mul.rn.f32x2 %0, %1, %2;" : "=l"(d) : "l"(a), "l"(b)); return d;
}
__device__ __forceinline__ ull add2(ull a, ull b) {
    ull d; asm("add.rn.f32x2 %0, %1, %2;" : "=l"(d) : "l"(a), "l"(b)); return d;
}
__device__ __forceinline__ ull fma2(ull a, ull b, ull c) {
    ull d; asm("fma.rn.f32x2 %0, %1, %2, %3;" : "=l"(d) : "l"(a), "l"(b), "l"(c)); return d;
}

// ---- cp.async helpers ------------------------------------------------------
__device__ __forceinline__ void cpasync16(void* smem, const void* gmem) {
    unsigned sa = (unsigned)__cvta_generic_to_shared(smem);
    asm volatile("cp.async.cg.shared.global [%0], [%1], 16;" :: "r"(sa), "l"(gmem));
}
__device__ __forceinline__ void cpasync_commit() {
    asm volatile("cp.async.commit_group;");
}
template <int N>
__device__ __forceinline__ void cpasync_wait() {
    asm volatile("cp.async.wait_group %0;" :: "n"(N));
}

// ---------------------------------------------------------------------------
// Transpose (float4 both ways, 64x64 tiles): g_imgT[a*512+b] = img[b*512+a].
// Also re-zeroes the per-theta tickets every launch (graph replays!).
// ---------------------------------------------------------------------------
__global__ void dht_transpose(const float* __restrict__ img) {
    __shared__ float tile[64][65];
    const int tid = threadIdx.x;
    if (blockIdx.x == 0 && tid < NUM_T) g_ticket[tid] = 0;

    const int bx = (blockIdx.x & 7) * 64;
    const int by = (blockIdx.x >> 3) * 64;
    const int tx = tid & 15;           // float4 column 0..15
    const int ty = tid >> 4;           // row 0..15

#pragma unroll
    for (int i = 0; i < 64; i += 16) {
        float4 v = *(const float4*)&img[(size_t)(by + ty + i) * IMG_N + bx + tx * 4];
        tile[ty + i][tx * 4 + 0] = v.x;
        tile[ty + i][tx * 4 + 1] = v.y;
        tile[ty + i][tx * 4 + 2] = v.z;
        tile[ty + i][tx * 4 + 3] = v.w;
    }
    __syncthreads();
#pragma unroll
    for (int i = 0; i < 64; i += 16) {
        int a = ty + i;
        float4 v;
        v.x = tile[tx * 4 + 0][a];
        v.y = tile[tx * 4 + 1][a];
        v.z = tile[tx * 4 + 2][a];
        v.w = tile[tx * 4 + 3][a];
        *(float4*)&g_imgT[(size_t)(bx + a) * IMG_N + by + tx * 4] = v;
    }
}

// ---------------------------------------------------------------------------
// Main Hough kernel (R8 body). blockIdx.x = theta, blockIdx.y = n-split.
// Warp w owns rhos [96w, 96w+96); lane l handles r = 96w + 32k + l, k=0..2
// (lane stride ~2 words in smem -> ~2-way LDS conflict).
// Warp-uniform 4-corner band test skips whole (warp,chunk) tiles whose
// samples are all out of bounds (they'd add exactly +0.0f).
// Zero-padded smem rows (row[512]=0): OOB index -> min(u,512) -> reads 0.
// Tail: threadfence-ticket; the last n-split block per theta reduces the 4
// partials in fixed sp order (deterministic, bit-identical) and writes out.
// ---------------------------------------------------------------------------
__global__ __launch_bounds__(TB, 5) void dht_main(const float* __restrict__ img,
                                                  float* __restrict__ out) {
    __shared__ float buf[2][CHUNK * ROWSTRIDE];   // 33 KB
    __shared__ int ticket_s;

    const int t   = blockIdx.x;
    const int sp  = blockIdx.y;
    const int tid = threadIdx.x;
    const int w   = tid >> 5;
    const int ln  = tid & 31;

    // theta = t * f32(pi/180); libdevice cos/sin on the identical f32 theta.
    const float theta = __fmul_rn((float)t, 0.017453292519943295f);
    const float c = cosf(theta);
    const float s = sinf(theta);
    const bool use_x = fabsf(s) >= fabsf(c);

    const float* __restrict__ src = use_x ? img : g_imgT;
    const float den  = use_x ? s : c;
    const float coef = use_x ? c : s;

    const float rden  = __fdiv_rn(1.0f, den);   // correctly-rounded seed
    const float nden  = -den;
    const float ncoef = -coef;

    // rho table: f32 linspace(-diag, diag, 725).
    const float diag  = __fsqrt_rn(524288.0f);
    const float delta = __fdiv_rn(__fadd_rn(diag, diag), 724.0f);
    const float ndiag = -diag;

    const int r0 = 96 * w + ln, r1 = r0 + 32, r2 = r0 + 64;
    const float rho0 = (r0 == NUM_R - 1) ? diag : __fadd_rn(ndiag, __fmul_rn((float)r0, delta));
    const float rho1 = (r1 == NUM_R - 1) ? diag : __fadd_rn(ndiag, __fmul_rn((float)r1, delta));
    const float rho2 = (r2 == NUM_R - 1) ? diag : __fadd_rn(ndiag, __fmul_rn((float)r2, delta));

    const ull rho01  = pk2(rho0, rho1);
    const ull rden2  = pk2(rden, rden);
    const ull nden2  = pk2(nden, nden);
    const ull ncoef2 = pk2(ncoef, ncoef);
    const ull ones2  = pk2(1.0f, 1.0f);

    // Warp-uniform rho bounds for the band test (+/- delta slack).
    const float rhoA = ndiag + ((float)(96 * w) - 1.0f) * delta;
    const float rhoB = ndiag + ((float)(96 * w + 95) + 1.0f) * delta;

    const int nbase0 = sp * NROWS;

    float acc0 = 0.0f, acc1 = 0.0f, acc2 = 0.0f;

    // Zero the pad slots of both buffers once (cp.async never touches them).
    if (tid < 2 * CHUNK) {
        int b = tid >> 3, j = tid & 7;
        *(float4*)(&buf[b][j * ROWSTRIDE + IMG_N]) = make_float4(0.f, 0.f, 0.f, 0.f);
    }

    const float4* __restrict__ gbase = (const float4*)(src + (size_t)nbase0 * IMG_N);

    // Prologue: prefetch chunk 0 into buffer 0.
    {
#pragma unroll
        for (int l = 0; l < 4; l++) {
            int idx = tid + l * TB;            // 0..1023
            int jr = idx >> 7, cx = idx & 127;
            cpasync16(&((float4*)(&buf[0][jr * ROWSTRIDE]))[cx], &gbase[idx]);
        }
        cpasync_commit();
    }

    for (int cb = 0; cb < NCHUNK; cb++) {
        if (cb + 1 < NCHUNK) {                 // prefetch next chunk
            const float4* g = gbase + (size_t)(cb + 1) * CHUNK * (IMG_N / 4);
            float* bnext = buf[(cb + 1) & 1];
#pragma unroll
            for (int l = 0; l < 4; l++) {
                int idx = tid + l * TB;
                int jr = idx >> 7, cx = idx & 127;
                cpasync16(&((float4*)(bnext + jr * ROWSTRIDE))[cx], &g[idx]);
            }
            cpasync_commit();
            cpasync_wait<1>();                 // chunk cb complete
        } else {
            cpasync_wait<0>();
        }
        __syncthreads();                       // data visible to all warps

        // ---- warp-uniform band test: can any sample in this tile land? ----
        const float n0f = (float)(nbase0 + cb * CHUNK);
        const float n1f = n0f + (float)(CHUNK - 1);
        float y00 = (rhoA - n0f * coef) * rden;
        float y01 = (rhoA - n1f * coef) * rden;
        float y10 = (rhoB - n0f * coef) * rden;
        float y11 = (rhoB - n1f * coef) * rden;
        float ymin = fminf(fminf(y00, y01), fminf(y10, y11));
        float ymax = fmaxf(fmaxf(y00, y01), fmaxf(y10, y11));

        if (ymax >= -4.0f && ymin <= (float)IMG_N + 4.0f) {
            const float* __restrict__ bcur = buf[cb & 1];
            ull nf2 = pk2(n0f, n0f);
#pragma unroll 4
            for (int j = 0; j < CHUNK; j++) {
                const float* __restrict__ row = bcur + j * ROWSTRIDE;

                // packed pair (rho0, rho1): num = RN(rho + RN(n * -coef))
                ull nnc2 = mul2(nf2, ncoef2);
                float nncs, nnch; upk2(nncs, nnch, nnc2);   // lo = n*(-coef)
                ull num2 = add2(rho01, nnc2);
                ull q02  = mul2(num2, rden2);
                ull e2   = fma2(nden2, q02, num2);
                ull q2   = fma2(e2, rden2, q02);   // = RN(num/den) exactly
                float qa, qb; upk2(qa, qb, q2);

                // scalar rho2 (reuses packed n*(-coef) product)
                float nums = __fadd_rn(rho2, nncs);
                float q0s  = __fmul_rn(nums, rden);
                float qs   = __fmaf_rn(__fmaf_rn(nden, q0s, nums), rden, q0s);

                int y0 = __float2int_rn(qa);
                int y1 = __float2int_rn(qb);
                int y2 = __float2int_rn(qs);
                unsigned u0 = min((unsigned)y0, (unsigned)IMG_N);  // OOB -> pad (0.0f)
                unsigned u1 = min((unsigned)y1, (unsigned)IMG_N);
                unsigned u2 = min((unsigned)y2, (unsigned)IMG_N);
                acc0 = __fadd_rn(acc0, row[u0]);
                acc1 = __fadd_rn(acc1, row[u1]);
                acc2 = __fadd_rn(acc2, row[u2]);

                nf2 = add2(nf2, ones2);
            }
        }
        __syncthreads();                       // compute done before buffer reuse
    }

    // Partial-sum stores: scratch[sp][t][r] (32-wide coalesced segments).
    float* dst = g_scratch + ((size_t)sp * NUM_T + t) * NUM_R;
    dst[r0] = acc0;
    if (r1 < NUM_R) dst[r1] = acc1;
    if (r2 < NUM_R) dst[r2] = acc2;

    // ---- fused deterministic reduction (threadfence-ticket pattern) -------
    __threadfence();                           // partials visible device-wide
    __syncthreads();                           // all stores issued before ticket
    if (tid == 0) ticket_s = atomicAdd(&g_ticket[t], 1);
    __syncthreads();
    if (ticket_s == NSPLIT - 1) {              // last block for this theta
        for (int r = tid; r < NUM_R; r += TB) {
            float v = g_scratch[(size_t)t * NUM_R + r];          // sp = 0
#pragma unroll
            for (int spp = 1; spp < NSPLIT; spp++)
                v = __fadd_rn(v, g_scratch[((size_t)spp * NUM_T + t) * NUM_R + r]);
            out[r * NUM_T + t] = v;
        }
    }
}

// ---------------------------------------------------------------------------
extern "C" void kernel_launch(void* const* d_in, const int* in_sizes, int n_in,
                              void* d_out, int out_size) {
    const float* img = (const float*)d_in[0];
    float* out = (float*)d_out;

    dht_transpose<<<64, 256>>>(img);
    dht_main<<<dim3(NUM_T, NSPLIT), TB>>>(img, out);
}

// round 12
// speedup vs baseline: 1.0585x; 1.0451x over previous
#include <cuda_runtime.h>

#define NUM_R 725
#define NUM_T 180
#define IMG_N 512
#define NSPLIT 4                 // n-dimension split
#define TB 256                   // threads per block
#define NROWS (IMG_N / NSPLIT)   // 128 sweep rows per block
#define CHUNK 8                  // rows per pipeline stage
#define ROWSTRIDE 516            // 512 data + 4 pad floats (16B-aligned)
#define NCHUNK (NROWS / CHUNK)   // 16 stages
#define NPAIR 92                 // theta pair-slots (88 pairs + 4 solos)

// Scratch (device globals per the allocation-free rule)
__device__ float g_imgT[IMG_N * IMG_N];                 // transposed image
__device__ float g_scratch[NSPLIT * NUM_T * NUM_R];     // partials [sp][t][r]

typedef unsigned long long ull;

// ---- packed f32x2 helpers (Blackwell) --------------------------------------
__device__ __forceinline__ ull pk2(float lo, float hi) {
    ull r; asm("mov.b64 %0, {%1, %2};" : "=l"(r) : "f"(lo), "f"(hi)); return r;
}
__device__ __forceinline__ void upk2(float& lo, float& hi, ull v) {
    asm("mov.b64 {%0, %1}, %2;" : "=f"(lo), "=f"(hi) : "l"(v));
}
__device__ __forceinline__ ull mul2(ull a, ull b) {
    ull d; asm("mul.rn.f32x2 %0, %1, %2;" : "=l"(d) : "l"(a), "l"(b)); return d;
}
__device__ __forceinline__ ull add2(ull a, ull b) {
    ull d; asm("add.rn.f32x2 %0, %1, %2;" : "=l"(d) : "l"(a), "l"(b)); return d;
}
__device__ __forceinline__ ull fma2(ull a, ull b, ull c) {
    ull d; asm("fma.rn.f32x2 %0, %1, %2, %3;" : "=l"(d) : "l"(a), "l"(b), "l"(c)); return d;
}

// ---- cp.async helpers ------------------------------------------------------
__device__ __forceinline__ void cpasync16(void* smem, const void* gmem) {
    unsigned sa = (unsigned)__cvta_generic_to_shared(smem);
    asm volatile("cp.async.cg.shared.global [%0], [%1], 16;" :: "r"(sa), "l"(gmem));
}
__device__ __forceinline__ void cpasync_commit() {
    asm volatile("cp.async.commit_group;");
}
template <int N>
__device__ __forceinline__ void cpasync_wait() {
    asm volatile("cp.async.wait_group %0;" :: "n"(N));
}

// ---------------------------------------------------------------------------
// Transpose (float4 both ways, 64x64 tiles): g_imgT[a*512+b] = img[b*512+a].
// ---------------------------------------------------------------------------
__global__ void dht_transpose(const float* __restrict__ img) {
    __shared__ float tile[64][65];
    const int tid = threadIdx.x;
    const int bx = (blockIdx.x & 7) * 64;
    const int by = (blockIdx.x >> 3) * 64;
    const int tx = tid & 15;           // float4 column 0..15
    const int ty = tid >> 4;           // row 0..15

#pragma unroll
    for (int i = 0; i < 64; i += 16) {
        float4 v = *(const float4*)&img[(size_t)(by + ty + i) * IMG_N + bx + tx * 4];
        tile[ty + i][tx * 4 + 0] = v.x;
        tile[ty + i][tx * 4 + 1] = v.y;
        tile[ty + i][tx * 4 + 2] = v.z;
        tile[ty + i][tx * 4 + 3] = v.w;
    }
    __syncthreads();
#pragma unroll
    for (int i = 0; i < 64; i += 16) {
        int a = ty + i;
        float4 v;
        v.x = tile[tx * 4 + 0][a];
        v.y = tile[tx * 4 + 1][a];
        v.z = tile[tx * 4 + 2][a];
        v.w = tile[tx * 4 + 3][a];
        *(float4*)&g_imgT[(size_t)(bx + a) * IMG_N + by + tx * 4] = v;
    }
}

// ---------------------------------------------------------------------------
// Main Hough kernel, theta-paired. blockIdx.x = pair slot, blockIdx.y = split.
// Each block serves TWO adjacent same-class thetas from ONE staged chunk
// stream (halves L2 traffic + barrier count per unit work). Warp w owns rhos
// [96w, 96w+96); lane l handles r = 96w + 32k + l (k=0..2); rho table is
// theta-independent. One union 8-corner band test per chunk skips dead tiles
// (all samples OOB -> +0.0f). Zero-padded smem rows: OOB -> min(u,512) -> 0.
// Solo slots (theta 44,45,134,135; class ambiguous or unpaired) run with
// t1 = t0 and suppressed second stores.
// ---------------------------------------------------------------------------
__global__ __launch_bounds__(TB, 4) void dht_main(const float* __restrict__ img) {
    __shared__ float buf[2][CHUNK * ROWSTRIDE];   // 33 KB

    const int p   = blockIdx.x;
    const int sp  = blockIdx.y;
    const int tid = threadIdx.x;
    const int w   = tid >> 5;
    const int ln  = tid & 31;

    // ---- pair-slot -> (t0, t1) mapping (same f32 class within each pair) --
    int t0, t1;
    if      (p <  44) { t0 = 46 + 2 * p;        t1 = t0 + 1; }   // X: 46..133
    else if (p == 44) { t0 = 134;               t1 = -1;     }   // X solo
    else if (p == 45) { t0 = 45;                t1 = -1;     }   // boundary solo
    else if (p <  68) { int j = p - 46; t0 = 2 * j;       t1 = t0 + 1; } // Y: 0..43
    else if (p == 68) { t0 = 44;                t1 = -1;     }   // Y solo
    else if (p <  91) { int j = p - 69; t0 = 136 + 2 * j; t1 = t0 + 1; } // Y: 136..179
    else              { t0 = 135;               t1 = -1;     }   // boundary solo
    const bool dual = (t1 >= 0);
    const int  tb   = dual ? t1 : t0;

    // ---- per-theta constants (identical arithmetic to reference) ----------
    const float thetaA = __fmul_rn((float)t0, 0.017453292519943295f);
    const float cA = cosf(thetaA), sA = sinf(thetaA);
    const bool use_x = fabsf(sA) >= fabsf(cA);
    const float denA  = use_x ? sA : cA;
    const float coefA = use_x ? cA : sA;
    const float rdenA = __fdiv_rn(1.0f, denA);
    const float ndenA = -denA;
    const float ncoefA = -coefA;

    const float thetaB = __fmul_rn((float)tb, 0.017453292519943295f);
    const float cB = cosf(thetaB), sB = sinf(thetaB);
    const bool use_xB = fabsf(sB) >= fabsf(cB);  // == use_x for all pairs (margin >= 0.017)
    const float denB  = use_xB ? sB : cB;
    const float coefB = use_xB ? cB : sB;
    const float rdenB = __fdiv_rn(1.0f, denB);
    const float ndenB = -denB;
    const float ncoefB = -coefB;

    const float* __restrict__ src = use_x ? img : g_imgT;

    // rho table: f32 linspace(-diag, diag, 725) (theta-independent).
    const float diag  = __fsqrt_rn(524288.0f);
    const float delta = __fdiv_rn(__fadd_rn(diag, diag), 724.0f);
    const float ndiag = -diag;

    const int r0 = 96 * w + ln, r1 = r0 + 32, r2 = r0 + 64;
    const float rho0 = (r0 == NUM_R - 1) ? diag : __fadd_rn(ndiag, __fmul_rn((float)r0, delta));
    const float rho1 = (r1 == NUM_R - 1) ? diag : __fadd_rn(ndiag, __fmul_rn((float)r1, delta));
    const float rho2 = (r2 == NUM_R - 1) ? diag : __fadd_rn(ndiag, __fmul_rn((float)r2, delta));

    const ull rho01   = pk2(rho0, rho1);
    const ull ones2   = pk2(1.0f, 1.0f);
    const ull rden2A  = pk2(rdenA, rdenA);
    const ull nden2A  = pk2(ndenA, ndenA);
    const ull ncoef2A = pk2(ncoefA, ncoefA);
    const ull rden2B  = pk2(rdenB, rdenB);
    const ull nden2B  = pk2(ndenB, ndenB);
    const ull ncoef2B = pk2(ncoefB, ncoefB);

    // Warp-uniform rho bounds for the band test (+/- delta slack).
    const float rhoA = ndiag + ((float)(96 * w) - 1.0f) * delta;
    const float rhoB = ndiag + ((float)(96 * w + 95) + 1.0f) * delta;

    const int nbase0 = sp * NROWS;

    float a0A = 0.0f, a1A = 0.0f, a2A = 0.0f;
    float a0B = 0.0f, a1B = 0.0f, a2B = 0.0f;

    // Zero the pad slots of both buffers once (cp.async never touches them).
    if (tid < 2 * CHUNK) {
        int b = tid >> 3, j = tid & 7;
        *(float4*)(&buf[b][j * ROWSTRIDE + IMG_N]) = make_float4(0.f, 0.f, 0.f, 0.f);
    }

    const float4* __restrict__ gbase = (const float4*)(src + (size_t)nbase0 * IMG_N);

    // Prologue: prefetch chunk 0 into buffer 0.
    {
#pragma unroll
        for (int l = 0; l < 4; l++) {
            int idx = tid + l * TB;            // 0..1023
            int jr = idx >> 7, cx = idx & 127;
            cpasync16(&((float4*)(&buf[0][jr * ROWSTRIDE]))[cx], &gbase[idx]);
        }
        cpasync_commit();
    }

    for (int cb = 0; cb < NCHUNK; cb++) {
        if (cb + 1 < NCHUNK) {                 // prefetch next chunk
            const float4* g = gbase + (size_t)(cb + 1) * CHUNK * (IMG_N / 4);
            float* bnext = buf[(cb + 1) & 1];
#pragma unroll
            for (int l = 0; l < 4; l++) {
                int idx = tid + l * TB;
                int jr = idx >> 7, cx = idx & 127;
                cpasync16(&((float4*)(bnext + jr * ROWSTRIDE))[cx], &g[idx]);
            }
            cpasync_commit();
            cpasync_wait<1>();                 // chunk cb complete
        } else {
            cpasync_wait<0>();
        }
        __syncthreads();                       // data visible to all warps

        // ---- union band test over both thetas (8 corners) -----------------
        const float n0f = (float)(nbase0 + cb * CHUNK);
        const float n1f = n0f + (float)(CHUNK - 1);
        float yA00 = (rhoA - n0f * coefA) * rdenA;
        float yA01 = (rhoA - n1f * coefA) * rdenA;
        float yA10 = (rhoB - n0f * coefA) * rdenA;
        float yA11 = (rhoB - n1f * coefA) * rdenA;
        float yB00 = (rhoA - n0f * coefB) * rdenB;
        float yB01 = (rhoA - n1f * coefB) * rdenB;
        float yB10 = (rhoB - n0f * coefB) * rdenB;
        float yB11 = (rhoB - n1f * coefB) * rdenB;
        float mnA = fminf(fminf(yA00, yA01), fminf(yA10, yA11));
        float mxA = fmaxf(fmaxf(yA00, yA01), fmaxf(yA10, yA11));
        float mnB = fminf(fminf(yB00, yB01), fminf(yB10, yB11));
        float mxB = fmaxf(fmaxf(yB00, yB01), fmaxf(yB10, yB11));
        const float hi = (float)IMG_N + 4.0f;
        bool live = (fmaxf(mxA, mxB) >= -4.0f) && (fminf(mnA, mnB) <= hi);

        if (live) {
            const float* __restrict__ bcur = buf[cb & 1];
            ull nf2 = pk2(n0f, n0f);
            float nfs = n0f;
#pragma unroll 2
            for (int j = 0; j < CHUNK; j++) {
                const float* __restrict__ row = bcur + j * ROWSTRIDE;

                // ---------- theta A: packed (rho0,rho1) + scalar rho2 ------
                ull nnc2A = mul2(nf2, ncoef2A);
                float nnlA, nnhA; upk2(nnlA, nnhA, nnc2A);     // lo = n*(-coefA)
                ull num2A = add2(rho01, nnc2A);
                ull q02A  = mul2(num2A, rden2A);
                ull e2A   = fma2(nden2A, q02A, num2A);
                ull q2A   = fma2(e2A, rden2A, q02A);           // RN(num/den)
                float qaA, qbA; upk2(qaA, qbA, q2A);
                float numsA = __fadd_rn(rho2, nnlA);
                float q0sA  = __fmul_rn(numsA, rdenA);
                float qsA   = __fmaf_rn(__fmaf_rn(ndenA, q0sA, numsA), rdenA, q0sA);

                // ---------- theta B ----------------------------------------
                ull nnc2B = mul2(nf2, ncoef2B);
                float nnlB, nnhB; upk2(nnlB, nnhB, nnc2B);
                ull num2B = add2(rho01, nnc2B);
                ull q02B  = mul2(num2B, rden2B);
                ull e2B   = fma2(nden2B, q02B, num2B);
                ull q2B   = fma2(e2B, rden2B, q02B);
                float qaB, qbB; upk2(qaB, qbB, q2B);
                float numsB = __fadd_rn(rho2, nnlB);
                float q0sB  = __fmul_rn(numsB, rdenB);
                float qsB   = __fmaf_rn(__fmaf_rn(ndenB, q0sB, numsB), rdenB, q0sB);

                // ---------- gathers (zero-pad OOB) -------------------------
                unsigned u0A = min((unsigned)__float2int_rn(qaA), (unsigned)IMG_N);
                unsigned u1A = min((unsigned)__float2int_rn(qbA), (unsigned)IMG_N);
                unsigned u2A = min((unsigned)__float2int_rn(qsA), (unsigned)IMG_N);
                unsigned u0B = min((unsigned)__float2int_rn(qaB), (unsigned)IMG_N);
                unsigned u1B = min((unsigned)__float2int_rn(qbB), (unsigned)IMG_N);
                unsigned u2B = min((unsigned)__float2int_rn(qsB), (unsigned)IMG_N);
                a0A = __fadd_rn(a0A, row[u0A]);
                a1A = __fadd_rn(a1A, row[u1A]);
                a2A = __fadd_rn(a2A, row[u2A]);
                a0B = __fadd_rn(a0B, row[u0B]);
                a1B = __fadd_rn(a1B, row[u1B]);
                a2B = __fadd_rn(a2B, row[u2B]);

                nf2 = add2(nf2, ones2);
                nfs = __fadd_rn(nfs, 1.0f);
            }
        }
        __syncthreads();                       // compute done before buffer reuse
    }

    // Partial-sum stores: scratch[sp][t][r] (32-wide coalesced segments).
    float* dst0 = g_scratch + ((size_t)sp * NUM_T + t0) * NUM_R;
    dst0[r0] = a0A;
    if (r1 < NUM_R) dst0[r1] = a1A;
    if (r2 < NUM_R) dst0[r2] = a2A;
    if (dual) {
        float* dst1 = g_scratch + ((size_t)sp * NUM_T + t1) * NUM_R;
        dst1[r0] = a0B;
        if (r1 < NUM_R) dst1[r1] = a1B;
        if (r2 < NUM_R) dst1[r2] = a2B;
    }
}

// ---------------------------------------------------------------------------
// Deterministic reduce over NSPLIT partials; out[r*180 + t].
// ---------------------------------------------------------------------------
__global__ void dht_reduce(float* __restrict__ out) {
    int i = blockIdx.x * 256 + threadIdx.x;     // i = t*NUM_R + r
    if (i < NUM_T * NUM_R) {
        float v = g_scratch[i];
#pragma unroll
        for (int sp = 1; sp < NSPLIT; sp++)
            v = __fadd_rn(v, g_scratch[(size_t)sp * NUM_T * NUM_R + i]);
        int t = i / NUM_R;
        int r = i - t * NUM_R;
        out[r * NUM_T + t] = v;
    }
}

// ---------------------------------------------------------------------------
extern "C" void kernel_launch(void* const* d_in, const int* in_sizes, int n_in,
                              void* d_out, int out_size) {
    const float* img = (const float*)d_in[0];
    float* out = (float*)d_out;

    dht_transpose<<<64, 256>>>(img);
    dht_main<<<dim3(NPAIR, NSPLIT), TB>>>(img);
    dht_reduce<<<(NUM_T * NUM_R + 255) / 256, 256>>>(out);
}

// round 13
// speedup vs baseline: 1.2056x; 1.1390x over previous
#include <cuda_runtime.h>

#define NUM_R 725
#define NUM_T 180
#define IMG_N 512
#define NSPLIT 8                 // n-dimension split (92x8=736 blocks ~ 1 wave @5/SM)
#define TB 256                   // threads per block
#define NROWS (IMG_N / NSPLIT)   // 64 sweep rows per block
#define CHUNK 8                  // rows per pipeline stage
#define ROWSTRIDE 516            // 512 data + 4 pad floats (16B-aligned)
#define NCHUNK (NROWS / CHUNK)   // 8 stages
#define NPAIR 92                 // theta pair-slots (88 pairs + 4 solos)

// Scratch (device globals per the allocation-free rule)
__device__ float g_imgT[IMG_N * IMG_N];                 // transposed image
__device__ float g_scratch[NSPLIT * NUM_T * NUM_R];     // partials [sp][t][r]

typedef unsigned long long ull;

// ---- packed f32x2 helpers (Blackwell) --------------------------------------
__device__ __forceinline__ ull pk2(float lo, float hi) {
    ull r; asm("mov.b64 %0, {%1, %2};" : "=l"(r) : "f"(lo), "f"(hi)); return r;
}
__device__ __forceinline__ void upk2(float& lo, float& hi, ull v) {
    asm("mov.b64 {%0, %1}, %2;" : "=f"(lo), "=f"(hi) : "l"(v));
}
__device__ __forceinline__ ull mul2(ull a, ull b) {
    ull d; asm("mul.rn.f32x2 %0, %1, %2;" : "=l"(d) : "l"(a), "l"(b)); return d;
}
__device__ __forceinline__ ull add2(ull a, ull b) {
    ull d; asm("add.rn.f32x2 %0, %1, %2;" : "=l"(d) : "l"(a), "l"(b)); return d;
}
__device__ __forceinline__ ull fma2(ull a, ull b, ull c) {
    ull d; asm("fma.rn.f32x2 %0, %1, %2, %3;" : "=l"(d) : "l"(a), "l"(b), "l"(c)); return d;
}

// ---- cp.async helpers ------------------------------------------------------
__device__ __forceinline__ void cpasync16(void* smem, const void* gmem) {
    unsigned sa = (unsigned)__cvta_generic_to_shared(smem);
    asm volatile("cp.async.cg.shared.global [%0], [%1], 16;" :: "r"(sa), "l"(gmem));
}
__device__ __forceinline__ void cpasync_commit() {
    asm volatile("cp.async.commit_group;");
}
template <int N>
__device__ __forceinline__ void cpasync_wait() {
    asm volatile("cp.async.wait_group %0;" :: "n"(N));
}

// ---------------------------------------------------------------------------
// Transpose (proven scalar 32x32 pattern, both phases conflict-free):
// g_imgT[a*512 + b] = img[b*512 + a]
// ---------------------------------------------------------------------------
__global__ void dht_transpose(const float* __restrict__ img) {
    __shared__ float tile[32][33];
    int bx = blockIdx.x * 32, by = blockIdx.y * 32;
    int tx = threadIdx.x, ty = threadIdx.y;
#pragma unroll
    for (int i = 0; i < 32; i += 8)
        tile[ty + i][tx] = img[(by + ty + i) * IMG_N + (bx + tx)];
    __syncthreads();
#pragma unroll
    for (int i = 0; i < 32; i += 8)
        g_imgT[(bx + ty + i) * IMG_N + (by + tx)] = tile[tx][ty + i];
}

// ---------------------------------------------------------------------------
// Main Hough kernel, theta-paired. blockIdx.x = pair slot, blockIdx.y = split.
// Each block serves TWO adjacent same-class thetas from ONE staged chunk
// stream (halves L2 traffic + barrier count per unit work). Warp w owns rhos
// [96w, 96w+96); lane l handles r = 96w + 32k + l (k=0..2); rho table is
// theta-independent. One union 8-corner band test per chunk skips dead tiles
// (all samples OOB -> +0.0f). Zero-padded smem rows: OOB -> min(u,512) -> 0.
// Solo slots (theta 44,45,134,135) run with second stores suppressed.
// ---------------------------------------------------------------------------
__global__ __launch_bounds__(TB, 5) void dht_main(const float* __restrict__ img) {
    __shared__ float buf[2][CHUNK * ROWSTRIDE];   // 33 KB

    const int p   = blockIdx.x;
    const int sp  = blockIdx.y;
    const int tid = threadIdx.x;
    const int w   = tid >> 5;
    const int ln  = tid & 31;

    // ---- pair-slot -> (t0, t1) mapping (same f32 class within each pair) --
    int t0, t1;
    if      (p <  44) { t0 = 46 + 2 * p;        t1 = t0 + 1; }   // X: 46..133
    else if (p == 44) { t0 = 134;               t1 = -1;     }   // X solo
    else if (p == 45) { t0 = 45;                t1 = -1;     }   // boundary solo
    else if (p <  68) { int j = p - 46; t0 = 2 * j;       t1 = t0 + 1; } // Y: 0..43
    else if (p == 68) { t0 = 44;                t1 = -1;     }   // Y solo
    else if (p <  91) { int j = p - 69; t0 = 136 + 2 * j; t1 = t0 + 1; } // Y: 136..179
    else              { t0 = 135;               t1 = -1;     }   // boundary solo
    const bool dual = (t1 >= 0);
    const int  tb   = dual ? t1 : t0;

    // ---- per-theta constants (identical arithmetic to reference) ----------
    const float thetaA = __fmul_rn((float)t0, 0.017453292519943295f);
    const float cA = cosf(thetaA), sA = sinf(thetaA);
    const bool use_x = fabsf(sA) >= fabsf(cA);
    const float denA  = use_x ? sA : cA;
    const float coefA = use_x ? cA : sA;
    const float rdenA = __fdiv_rn(1.0f, denA);
    const float ndenA = -denA;
    const float ncoefA = -coefA;

    const float thetaB = __fmul_rn((float)tb, 0.017453292519943295f);
    const float cB = cosf(thetaB), sB = sinf(thetaB);
    const bool use_xB = fabsf(sB) >= fabsf(cB);  // == use_x within every pair
    const float denB  = use_xB ? sB : cB;
    const float coefB = use_xB ? cB : sB;
    const float rdenB = __fdiv_rn(1.0f, denB);
    const float ndenB = -denB;
    const float ncoefB = -coefB;

    const float* __restrict__ src = use_x ? img : g_imgT;

    // rho table: f32 linspace(-diag, diag, 725) (theta-independent).
    const float diag  = __fsqrt_rn(524288.0f);
    const float delta = __fdiv_rn(__fadd_rn(diag, diag), 724.0f);
    const float ndiag = -diag;

    const int r0 = 96 * w + ln, r1 = r0 + 32, r2 = r0 + 64;
    const float rho0 = (r0 == NUM_R - 1) ? diag : __fadd_rn(ndiag, __fmul_rn((float)r0, delta));
    const float rho1 = (r1 == NUM_R - 1) ? diag : __fadd_rn(ndiag, __fmul_rn((float)r1, delta));
    const float rho2 = (r2 == NUM_R - 1) ? diag : __fadd_rn(ndiag, __fmul_rn((float)r2, delta));

    const ull rho01   = pk2(rho0, rho1);
    const ull ones2   = pk2(1.0f, 1.0f);
    const ull rden2A  = pk2(rdenA, rdenA);
    const ull nden2A  = pk2(ndenA, ndenA);
    const ull ncoef2A = pk2(ncoefA, ncoefA);
    const ull rden2B  = pk2(rdenB, rdenB);
    const ull nden2B  = pk2(ndenB, ndenB);
    const ull ncoef2B = pk2(ncoefB, ncoefB);

    // Warp-uniform rho bounds for the band test (+/- delta slack).
    const float rhoA = ndiag + ((float)(96 * w) - 1.0f) * delta;
    const float rhoB = ndiag + ((float)(96 * w + 95) + 1.0f) * delta;

    const int nbase0 = sp * NROWS;

    float a0A = 0.0f, a1A = 0.0f, a2A = 0.0f;
    float a0B = 0.0f, a1B = 0.0f, a2B = 0.0f;

    // Zero the pad slots of both buffers once (cp.async never touches them).
    if (tid < 2 * CHUNK) {
        int b = tid >> 3, j = tid & 7;
        *(float4*)(&buf[b][j * ROWSTRIDE + IMG_N]) = make_float4(0.f, 0.f, 0.f, 0.f);
    }

    const float4* __restrict__ gbase = (const float4*)(src + (size_t)nbase0 * IMG_N);

    // Prologue: prefetch chunk 0 into buffer 0.
    {
#pragma unroll
        for (int l = 0; l < 4; l++) {
            int idx = tid + l * TB;            // 0..1023
            int jr = idx >> 7, cx = idx & 127;
            cpasync16(&((float4*)(&buf[0][jr * ROWSTRIDE]))[cx], &gbase[idx]);
        }
        cpasync_commit();
    }

    for (int cb = 0; cb < NCHUNK; cb++) {
        if (cb + 1 < NCHUNK) {                 // prefetch next chunk
            const float4* g = gbase + (size_t)(cb + 1) * CHUNK * (IMG_N / 4);
            float* bnext = buf[(cb + 1) & 1];
#pragma unroll
            for (int l = 0; l < 4; l++) {
                int idx = tid + l * TB;
                int jr = idx >> 7, cx = idx & 127;
                cpasync16(&((float4*)(bnext + jr * ROWSTRIDE))[cx], &g[idx]);
            }
            cpasync_commit();
            cpasync_wait<1>();                 // chunk cb complete
        } else {
            cpasync_wait<0>();
        }
        __syncthreads();                       // data visible to all warps

        // ---- union band test over both thetas (8 corners) -----------------
        const float n0f = (float)(nbase0 + cb * CHUNK);
        const float n1f = n0f + (float)(CHUNK - 1);
        float yA00 = (rhoA - n0f * coefA) * rdenA;
        float yA01 = (rhoA - n1f * coefA) * rdenA;
        float yA10 = (rhoB - n0f * coefA) * rdenA;
        float yA11 = (rhoB - n1f * coefA) * rdenA;
        float yB00 = (rhoA - n0f * coefB) * rdenB;
        float yB01 = (rhoA - n1f * coefB) * rdenB;
        float yB10 = (rhoB - n0f * coefB) * rdenB;
        float yB11 = (rhoB - n1f * coefB) * rdenB;
        float mx = fmaxf(fmaxf(fmaxf(yA00, yA01), fmaxf(yA10, yA11)),
                         fmaxf(fmaxf(yB00, yB01), fmaxf(yB10, yB11)));
        float mn = fminf(fminf(fminf(yA00, yA01), fminf(yA10, yA11)),
                         fminf(fminf(yB00, yB01), fminf(yB10, yB11)));
        bool live = (mx >= -4.0f) && (mn <= (float)IMG_N + 4.0f);

        if (live) {
            const float* __restrict__ bcur = buf[cb & 1];
            ull nf2 = pk2(n0f, n0f);
#pragma unroll 2
            for (int j = 0; j < CHUNK; j++) {
                const float* __restrict__ row = bcur + j * ROWSTRIDE;

                // ---------- theta A: packed (rho0,rho1) + scalar rho2 ------
                ull nnc2A = mul2(nf2, ncoef2A);
                float nnlA, nnhA; upk2(nnlA, nnhA, nnc2A);     // lo = n*(-coefA)
                ull num2A = add2(rho01, nnc2A);
                ull q02A  = mul2(num2A, rden2A);
                ull e2A   = fma2(nden2A, q02A, num2A);
                ull q2A   = fma2(e2A, rden2A, q02A);           // RN(num/den)
                float qaA, qbA; upk2(qaA, qbA, q2A);
                float numsA = __fadd_rn(rho2, nnlA);
                float q0sA  = __fmul_rn(numsA, rdenA);
                float qsA   = __fmaf_rn(__fmaf_rn(ndenA, q0sA, numsA), rdenA, q0sA);

                // ---------- theta B ----------------------------------------
                ull nnc2B = mul2(nf2, ncoef2B);
                float nnlB, nnhB; upk2(nnlB, nnhB, nnc2B);
                ull num2B = add2(rho01, nnc2B);
                ull q02B  = mul2(num2B, rden2B);
                ull e2B   = fma2(nden2B, q02B, num2B);
                ull q2B   = fma2(e2B, rden2B, q02B);
                float qaB, qbB; upk2(qaB, qbB, q2B);
                float numsB = __fadd_rn(rho2, nnlB);
                float q0sB  = __fmul_rn(numsB, rdenB);
                float qsB   = __fmaf_rn(__fmaf_rn(ndenB, q0sB, numsB), rdenB, q0sB);

                // ---------- gathers (zero-pad OOB) -------------------------
                unsigned u0A = min((unsigned)__float2int_rn(qaA), (unsigned)IMG_N);
                unsigned u1A = min((unsigned)__float2int_rn(qbA), (unsigned)IMG_N);
                unsigned u2A = min((unsigned)__float2int_rn(qsA), (unsigned)IMG_N);
                unsigned u0B = min((unsigned)__float2int_rn(qaB), (unsigned)IMG_N);
                unsigned u1B = min((unsigned)__float2int_rn(qbB), (unsigned)IMG_N);
                unsigned u2B = min((unsigned)__float2int_rn(qsB), (unsigned)IMG_N);
                a0A = __fadd_rn(a0A, row[u0A]);
                a1A = __fadd_rn(a1A, row[u1A]);
                a2A = __fadd_rn(a2A, row[u2A]);
                a0B = __fadd_rn(a0B, row[u0B]);
                a1B = __fadd_rn(a1B, row[u1B]);
                a2B = __fadd_rn(a2B, row[u2B]);

                nf2 = add2(nf2, ones2);
            }
        }
        __syncthreads();                       // compute done before buffer reuse
    }

    // Partial-sum stores: scratch[sp][t][r] (32-wide coalesced segments).
    float* dst0 = g_scratch + ((size_t)sp * NUM_T + t0) * NUM_R;
    dst0[r0] = a0A;
    if (r1 < NUM_R) dst0[r1] = a1A;
    if (r2 < NUM_R) dst0[r2] = a2A;
    if (dual) {
        float* dst1 = g_scratch + ((size_t)sp * NUM_T + t1) * NUM_R;
        dst1[r0] = a0B;
        if (r1 < NUM_R) dst1[r1] = a1B;
        if (r2 < NUM_R) dst1[r2] = a2B;
    }
}

// ---------------------------------------------------------------------------
// Deterministic reduce over NSPLIT partials (fixed sp order); out[r*180 + t].
// ---------------------------------------------------------------------------
__global__ void dht_reduce(float* __restrict__ out) {
    int i = blockIdx.x * 256 + threadIdx.x;     // i = t*NUM_R + r
    if (i < NUM_T * NUM_R) {
        float v = g_scratch[i];
#pragma unroll
        for (int sp = 1; sp < NSPLIT; sp++)
            v = __fadd_rn(v, g_scratch[(size_t)sp * NUM_T * NUM_R + i]);
        int t = i / NUM_R;
        int r = i - t * NUM_R;
        out[r * NUM_T + t] = v;
    }
}

// ---------------------------------------------------------------------------
extern "C" void kernel_launch(void* const* d_in, const int* in_sizes, int n_in,
                              void* d_out, int out_size) {
    const float* img = (const float*)d_in[0];
    float* out = (float*)d_out;

    dht_transpose<<<dim3(IMG_N / 32, IMG_N / 32), dim3(32, 8)>>>(img);
    dht_main<<<dim3(NPAIR, NSPLIT), TB>>>(img);
    dht_reduce<<<(NUM_T * NUM_R + 255) / 256, 256>>>(out);
}

// round 14
// speedup vs baseline: 1.2184x; 1.0106x over previous
#include <cuda_runtime.h>

#define NUM_R 725
#define NUM_T 180
#define IMG_N 512
#define NSPLIT 8                 // n-dimension split (92x8=736 blocks ~ 1 wave @5/SM)
#define TB 256                   // threads per block
#define NROWS (IMG_N / NSPLIT)   // 64 sweep rows per block
#define CHUNK 8                  // rows per pipeline stage
#define ROWSTRIDE 516            // 512 data + 4 pad floats (16B-aligned)
#define NCHUNK (NROWS / CHUNK)   // 8 stages
#define NPAIR 92                 // theta pair-slots (88 pairs + 4 solos)

// Scratch (device globals per the allocation-free rule)
__device__ float g_imgT[IMG_N * IMG_N];                 // transposed image
__device__ float g_scratch[NSPLIT * NUM_T * NUM_R];     // partials [sp][t][r]

typedef unsigned long long ull;

// ---- packed f32x2 helpers (Blackwell) --------------------------------------
__device__ __forceinline__ ull pk2(float lo, float hi) {
    ull r; asm("mov.b64 %0, {%1, %2};" : "=l"(r) : "f"(lo), "f"(hi)); return r;
}
__device__ __forceinline__ void upk2(float& lo, float& hi, ull v) {
    asm("mov.b64 {%0, %1}, %2;" : "=f"(lo), "=f"(hi) : "l"(v));
}
__device__ __forceinline__ ull mul2(ull a, ull b) {
    ull d; asm("mul.rn.f32x2 %0, %1, %2;" : "=l"(d) : "l"(a), "l"(b)); return d;
}
__device__ __forceinline__ ull add2(ull a, ull b) {
    ull d; asm("add.rn.f32x2 %0, %1, %2;" : "=l"(d) : "l"(a), "l"(b)); return d;
}
__device__ __forceinline__ ull fma2(ull a, ull b, ull c) {
    ull d; asm("fma.rn.f32x2 %0, %1, %2, %3;" : "=l"(d) : "l"(a), "l"(b), "l"(c)); return d;
}

// ---- cp.async helpers ------------------------------------------------------
__device__ __forceinline__ void cpasync16(void* smem, const void* gmem) {
    unsigned sa = (unsigned)__cvta_generic_to_shared(smem);
    asm volatile("cp.async.cg.shared.global [%0], [%1], 16;" :: "r"(sa), "l"(gmem));
}
__device__ __forceinline__ void cpasync_commit() {
    asm volatile("cp.async.commit_group;");
}
template <int N>
__device__ __forceinline__ void cpasync_wait() {
    asm volatile("cp.async.wait_group %0;" :: "n"(N));
}

// ---------------------------------------------------------------------------
// Transpose: g_imgT[a*512 + b] = img[b*512 + a].
// 64(a) x 32(b) tiles, 128 blocks x 256 threads.
// Load: 2x LDG.128 coalesced -> scalar STS (2-way, stride-65 rows).
// Store: 4x scalar LDS (banks 4*fq + k + a: all-distinct, conflict-free)
//        -> STG.128 coalesced.
// ---------------------------------------------------------------------------
__global__ void dht_transpose(const float* __restrict__ img) {
    __shared__ float tile[32][65];          // [b][a], row stride 65
    const int tid = threadIdx.x;
    const int bx = blockIdx.x * 64;         // a-base (8 blocks)
    const int by = blockIdx.y * 32;         // b-base (16 blocks)

    // Load phase: 512 float4 (32 b-rows x 16 f4), 2 per thread.
#pragma unroll
    for (int i = tid; i < 512; i += TB) {
        int row = i >> 4;                   // b offset 0..31
        int c4  = i & 15;                   // a float4 col 0..15
        float4 v = *(const float4*)&img[(size_t)(by + row) * IMG_N + bx + 4 * c4];
        tile[row][4 * c4 + 0] = v.x;
        tile[row][4 * c4 + 1] = v.y;
        tile[row][4 * c4 + 2] = v.z;
        tile[row][4 * c4 + 3] = v.w;
    }
    __syncthreads();

    // Store phase: 512 float4 (64 a-rows x 8 f4), 2 per thread.
#pragma unroll
    for (int i = tid; i < 512; i += TB) {
        int a  = i >> 3;                    // a offset 0..63
        int fq = i & 7;                     // b float4 col 0..7
        float4 v;
        v.x = tile[4 * fq + 0][a];
        v.y = tile[4 * fq + 1][a];
        v.z = tile[4 * fq + 2][a];
        v.w = tile[4 * fq + 3][a];
        *(float4*)&g_imgT[(size_t)(bx + a) * IMG_N + by + 4 * fq] = v;
    }
}

// ---------------------------------------------------------------------------
// Main Hough kernel, theta-paired (unchanged from R12 / 27.4us).
// blockIdx.x = pair slot, blockIdx.y = split. Each block serves TWO adjacent
// same-class thetas from ONE staged chunk stream. Warp w owns rhos
// [96w, 96w+96); lane l handles r = 96w + 32k + l (k=0..2). One union
// 8-corner band test per chunk skips dead tiles (all samples OOB -> +0.0f).
// Zero-padded smem rows: OOB -> min(u,512) -> reads 0.
// ---------------------------------------------------------------------------
__global__ __launch_bounds__(TB, 5) void dht_main(const float* __restrict__ img) {
    __shared__ float buf[2][CHUNK * ROWSTRIDE];   // 33 KB

    const int p   = blockIdx.x;
    const int sp  = blockIdx.y;
    const int tid = threadIdx.x;
    const int w   = tid >> 5;
    const int ln  = tid & 31;

    // ---- pair-slot -> (t0, t1) mapping (same f32 class within each pair) --
    int t0, t1;
    if      (p <  44) { t0 = 46 + 2 * p;        t1 = t0 + 1; }   // X: 46..133
    else if (p == 44) { t0 = 134;               t1 = -1;     }   // X solo
    else if (p == 45) { t0 = 45;                t1 = -1;     }   // boundary solo
    else if (p <  68) { int j = p - 46; t0 = 2 * j;       t1 = t0 + 1; } // Y: 0..43
    else if (p == 68) { t0 = 44;                t1 = -1;     }   // Y solo
    else if (p <  91) { int j = p - 69; t0 = 136 + 2 * j; t1 = t0 + 1; } // Y: 136..179
    else              { t0 = 135;               t1 = -1;     }   // boundary solo
    const bool dual = (t1 >= 0);
    const int  tb   = dual ? t1 : t0;

    // ---- per-theta constants (identical arithmetic to reference) ----------
    const float thetaA = __fmul_rn((float)t0, 0.017453292519943295f);
    const float cA = cosf(thetaA), sA = sinf(thetaA);
    const bool use_x = fabsf(sA) >= fabsf(cA);
    const float denA  = use_x ? sA : cA;
    const float coefA = use_x ? cA : sA;
    const float rdenA = __fdiv_rn(1.0f, denA);
    const float ndenA = -denA;
    const float ncoefA = -coefA;

    const float thetaB = __fmul_rn((float)tb, 0.017453292519943295f);
    const float cB = cosf(thetaB), sB = sinf(thetaB);
    const bool use_xB = fabsf(sB) >= fabsf(cB);  // == use_x within every pair
    const float denB  = use_xB ? sB : cB;
    const float coefB = use_xB ? cB : sB;
    const float rdenB = __fdiv_rn(1.0f, denB);
    const float ndenB = -denB;
    const float ncoefB = -coefB;

    const float* __restrict__ src = use_x ? img : g_imgT;

    // rho table: f32 linspace(-diag, diag, 725) (theta-independent).
    const float diag  = __fsqrt_rn(524288.0f);
    const float delta = __fdiv_rn(__fadd_rn(diag, diag), 724.0f);
    const float ndiag = -diag;

    const int r0 = 96 * w + ln, r1 = r0 + 32, r2 = r0 + 64;
    const float rho0 = (r0 == NUM_R - 1) ? diag : __fadd_rn(ndiag, __fmul_rn((float)r0, delta));
    const float rho1 = (r1 == NUM_R - 1) ? diag : __fadd_rn(ndiag, __fmul_rn((float)r1, delta));
    const float rho2 = (r2 == NUM_R - 1) ? diag : __fadd_rn(ndiag, __fmul_rn((float)r2, delta));

    const ull rho01   = pk2(rho0, rho1);
    const ull ones2   = pk2(1.0f, 1.0f);
    const ull rden2A  = pk2(rdenA, rdenA);
    const ull nden2A  = pk2(ndenA, ndenA);
    const ull ncoef2A = pk2(ncoefA, ncoefA);
    const ull rden2B  = pk2(rdenB, rdenB);
    const ull nden2B  = pk2(ndenB, ndenB);
    const ull ncoef2B = pk2(ncoefB, ncoefB);

    // Warp-uniform rho bounds for the band test (+/- delta slack).
    const float rhoA = ndiag + ((float)(96 * w) - 1.0f) * delta;
    const float rhoB = ndiag + ((float)(96 * w + 95) + 1.0f) * delta;

    const int nbase0 = sp * NROWS;

    float a0A = 0.0f, a1A = 0.0f, a2A = 0.0f;
    float a0B = 0.0f, a1B = 0.0f, a2B = 0.0f;

    // Zero the pad slots of both buffers once (cp.async never touches them).
    if (tid < 2 * CHUNK) {
        int b = tid >> 3, j = tid & 7;
        *(float4*)(&buf[b][j * ROWSTRIDE + IMG_N]) = make_float4(0.f, 0.f, 0.f, 0.f);
    }

    const float4* __restrict__ gbase = (const float4*)(src + (size_t)nbase0 * IMG_N);

    // Prologue: prefetch chunk 0 into buffer 0.
    {
#pragma unroll
        for (int l = 0; l < 4; l++) {
            int idx = tid + l * TB;            // 0..1023
            int jr = idx >> 7, cx = idx & 127;
            cpasync16(&((float4*)(&buf[0][jr * ROWSTRIDE]))[cx], &gbase[idx]);
        }
        cpasync_commit();
    }

    for (int cb = 0; cb < NCHUNK; cb++) {
        if (cb + 1 < NCHUNK) {                 // prefetch next chunk
            const float4* g = gbase + (size_t)(cb + 1) * CHUNK * (IMG_N / 4);
            float* bnext = buf[(cb + 1) & 1];
#pragma unroll
            for (int l = 0; l < 4; l++) {
                int idx = tid + l * TB;
                int jr = idx >> 7, cx = idx & 127;
                cpasync16(&((float4*)(bnext + jr * ROWSTRIDE))[cx], &g[idx]);
            }
            cpasync_commit();
            cpasync_wait<1>();                 // chunk cb complete
        } else {
            cpasync_wait<0>();
        }
        __syncthreads();                       // data visible to all warps

        // ---- union band test over both thetas (8 corners) -----------------
        const float n0f = (float)(nbase0 + cb * CHUNK);
        const float n1f = n0f + (float)(CHUNK - 1);
        float yA00 = (rhoA - n0f * coefA) * rdenA;
        float yA01 = (rhoA - n1f * coefA) * rdenA;
        float yA10 = (rhoB - n0f * coefA) * rdenA;
        float yA11 = (rhoB - n1f * coefA) * rdenA;
        float yB00 = (rhoA - n0f * coefB) * rdenB;
        float yB01 = (rhoA - n1f * coefB) * rdenB;
        float yB10 = (rhoB - n0f * coefB) * rdenB;
        float yB11 = (rhoB - n1f * coefB) * rdenB;
        float mx = fmaxf(fmaxf(fmaxf(yA00, yA01), fmaxf(yA10, yA11)),
                         fmaxf(fmaxf(yB00, yB01), fmaxf(yB10, yB11)));
        float mn = fminf(fminf(fminf(yA00, yA01), fminf(yA10, yA11)),
                         fminf(fminf(yB00, yB01), fminf(yB10, yB11)));
        bool live = (mx >= -4.0f) && (mn <= (float)IMG_N + 4.0f);

        if (live) {
            const float* __restrict__ bcur = buf[cb & 1];
            ull nf2 = pk2(n0f, n0f);
#pragma unroll 2
            for (int j = 0; j < CHUNK; j++) {
                const float* __restrict__ row = bcur + j * ROWSTRIDE;

                // ---------- theta A: packed (rho0,rho1) + scalar rho2 ------
                ull nnc2A = mul2(nf2, ncoef2A);
                float nnlA, nnhA; upk2(nnlA, nnhA, nnc2A);     // lo = n*(-coefA)
                ull num2A = add2(rho01, nnc2A);
                ull q02A  = mul2(num2A, rden2A);
                ull e2A   = fma2(nden2A, q02A, num2A);
                ull q2A   = fma2(e2A, rden2A, q02A);           // RN(num/den)
                float qaA, qbA; upk2(qaA, qbA, q2A);
                float numsA = __fadd_rn(rho2, nnlA);
                float q0sA  = __fmul_rn(numsA, rdenA);
                float qsA   = __fmaf_rn(__fmaf_rn(ndenA, q0sA, numsA), rdenA, q0sA);

                // ---------- theta B ----------------------------------------
                ull nnc2B = mul2(nf2, ncoef2B);
                float nnlB, nnhB; upk2(nnlB, nnhB, nnc2B);
                ull num2B = add2(rho01, nnc2B);
                ull q02B  = mul2(num2B, rden2B);
                ull e2B   = fma2(nden2B, q02B, num2B);
                ull q2B   = fma2(e2B, rden2B, q02B);
                float qaB, qbB; upk2(qaB, qbB, q2B);
                float numsB = __fadd_rn(rho2, nnlB);
                float q0sB  = __fmul_rn(numsB, rdenB);
                float qsB   = __fmaf_rn(__fmaf_rn(ndenB, q0sB, numsB), rdenB, q0sB);

                // ---------- gathers (zero-pad OOB) -------------------------
                unsigned u0A = min((unsigned)__float2int_rn(qaA), (unsigned)IMG_N);
                unsigned u1A = min((unsigned)__float2int_rn(qbA), (unsigned)IMG_N);
                unsigned u2A = min((unsigned)__float2int_rn(qsA), (unsigned)IMG_N);
                unsigned u0B = min((unsigned)__float2int_rn(qaB), (unsigned)IMG_N);
                unsigned u1B = min((unsigned)__float2int_rn(qbB), (unsigned)IMG_N);
                unsigned u2B = min((unsigned)__float2int_rn(qsB), (unsigned)IMG_N);
                a0A = __fadd_rn(a0A, row[u0A]);
                a1A = __fadd_rn(a1A, row[u1A]);
                a2A = __fadd_rn(a2A, row[u2A]);
                a0B = __fadd_rn(a0B, row[u0B]);
                a1B = __fadd_rn(a1B, row[u1B]);
                a2B = __fadd_rn(a2B, row[u2B]);

                nf2 = add2(nf2, ones2);
            }
        }
        __syncthreads();                       // compute done before buffer reuse
    }

    // Partial-sum stores: scratch[sp][t][r] (32-wide coalesced segments).
    float* dst0 = g_scratch + ((size_t)sp * NUM_T + t0) * NUM_R;
    dst0[r0] = a0A;
    if (r1 < NUM_R) dst0[r1] = a1A;
    if (r2 < NUM_R) dst0[r2] = a2A;
    if (dual) {
        float* dst1 = g_scratch + ((size_t)sp * NUM_T + t1) * NUM_R;
        dst1[r0] = a0B;
        if (r1 < NUM_R) dst1[r1] = a1B;
        if (r2 < NUM_R) dst1[r2] = a2B;
    }
}

// ---------------------------------------------------------------------------
// Deterministic reduce over NSPLIT partials (fixed sp order); out[r*180 + t].
// ---------------------------------------------------------------------------
__global__ void dht_reduce(float* __restrict__ out) {
    int i = blockIdx.x * 256 + threadIdx.x;     // i = t*NUM_R + r
    if (i < NUM_T * NUM_R) {
        float v = g_scratch[i];
#pragma unroll
        for (int sp = 1; sp < NSPLIT; sp++)
            v = __fadd_rn(v, g_scratch[(size_t)sp * NUM_T * NUM_R + i]);
        int t = i / NUM_R;
        int r = i - t * NUM_R;
        out[r * NUM_T + t] = v;
    }
}

// ---------------------------------------------------------------------------
extern "C" void kernel_launch(void* const* d_in, const int* in_sizes, int n_in,
                              void* d_out, int out_size) {
    const float* img = (const float*)d_in[0];
    float* out = (float*)d_out;

    dht_transpose<<<dim3(8, 16), 256>>>(img);
    dht_main<<<dim3(NPAIR, NSPLIT), TB>>>(img);
    dht_reduce<<<(NUM_T * NUM_R + 255) / 256, 256>>>(out);
}